// round 3
// baseline (speedup 1.0000x reference)
#include <cuda_runtime.h>
#include <cstdint>
#include <cstddef>

#define NUM_LAYERS 6

// ---------------------------------------------------------------------------
// Shapes:
//   x: (4,256,64,64) f32      y: (4,512) f32
//   ch_conv_w: (256,256)      ch_conv_b: (256)
//   affine_w: (6,256,512)     affine_b: (6,256)     mod_w: (6,256,256)
//   out: (4,256,128,128) f32
//
// Exact algebraic reductions:
//   * 2x2 spatial upsample commutes with all layers -> compute on 64x64 only
//   * channel repeat folded into conv weights (WU = Wc[j/2]+Wc[128+j/2], WB)
//   * wmod row-normalization is a closed-form per-row scalar alpha[b,o]
// State recurrence per conv pixel: u0=WU*x, b0=WB*x;
//   6x { h = WL[l,b]*u ; b += gelu(h) ; u += b } ; out = 0.5*u replicated 2x2.
//
// R2: cp.async double-buffered weight streaming (chunk=16 k-rows) to hide
// global latency inside the barrier-fenced GEMM loop; parallel prep_alpha.
// ---------------------------------------------------------------------------

__device__ float g_alpha[NUM_LAYERS * 4 * 256];
__device__ float g_WLt[NUM_LAYERS * 4 * 256 * 256];  // [l][b][k][o] = wmod[b,o,k]
__device__ float g_WUt[256 * 256];                   // [k][j]
__device__ float g_WBt[256 * 256];                   // [k][j]
__device__ float g_ub[256];
__device__ float g_bb[256];

// ---- prep: per-row modulation scalar alpha[b,o], parallel reduction -------
__global__ void prep_alpha(const float* __restrict__ affine_w,
                           const float* __restrict__ affine_b,
                           const float* __restrict__ mod_w,
                           const float* __restrict__ y) {
    int o = blockIdx.x;        // 0..255
    int lay = blockIdx.y;      // 0..5
    int t = threadIdx.x;       // 0..127
    const float* awr = affine_w + ((size_t)(lay * 256 + o)) * 512;
    float s0 = 0.f, s1 = 0.f, s2 = 0.f, s3 = 0.f, q = 0.f;
#pragma unroll
    for (int i = t; i < 512; i += 128) {
        float a = awr[i];
        s0 += a * y[i];
        s1 += a * y[512 + i];
        s2 += a * y[1024 + i];
        s3 += a * y[1536 + i];
    }
    const float* mwr = mod_w + ((size_t)(lay * 256 + o)) * 256;
#pragma unroll
    for (int i = t; i < 256; i += 128) { float m = mwr[i]; q += m * m; }
#pragma unroll
    for (int d = 16; d >= 1; d >>= 1) {
        s0 += __shfl_xor_sync(0xffffffffu, s0, d);
        s1 += __shfl_xor_sync(0xffffffffu, s1, d);
        s2 += __shfl_xor_sync(0xffffffffu, s2, d);
        s3 += __shfl_xor_sync(0xffffffffu, s3, d);
        q  += __shfl_xor_sync(0xffffffffu, q, d);
    }
    __shared__ float red[4][5];
    int w = t >> 5;
    if ((t & 31) == 0) {
        red[w][0] = s0; red[w][1] = s1; red[w][2] = s2; red[w][3] = s3; red[w][4] = q;
    }
    __syncthreads();
    if (t == 0) {
        float S[4], Q = 0.f;
        S[0] = S[1] = S[2] = S[3] = 0.f;
#pragma unroll
        for (int i = 0; i < 4; i++) {
            S[0] += red[i][0]; S[1] += red[i][1];
            S[2] += red[i][2]; S[3] += red[i][3]; Q += red[i][4];
        }
        float bias = affine_b[lay * 256 + o];
#pragma unroll
        for (int b = 0; b < 4; b++) {
            float sp = S[b] + bias + 1.f;
            g_alpha[(lay * 4 + b) * 256 + o] = sp * rsqrtf(sp * sp * Q + 1e-8f);
        }
    }
}

// ---- prep: scaled + transposed layer weights WLt[l][b][k][o] --------------
__global__ void prep_wl(const float* __restrict__ mod_w) {
    int lb = blockIdx.x;            // lay*4 + b
    int lay = lb >> 2;
    int o0 = blockIdx.y * 32, k0 = blockIdx.z * 32;
    int tx = threadIdx.x, ty = threadIdx.y;
    __shared__ float tile[32][33];
#pragma unroll
    for (int r = 0; r < 4; r++) {
        int oo = ty + r * 8;
        int o = o0 + oo;
        tile[oo][tx] = mod_w[((size_t)(lay * 256 + o)) * 256 + k0 + tx] *
                       g_alpha[lb * 256 + o];
    }
    __syncthreads();
    float* dst = g_WLt + ((size_t)lb << 16);
#pragma unroll
    for (int r = 0; r < 4; r++) {
        int kk = ty + r * 8;
        dst[(size_t)(k0 + kk) * 256 + o0 + tx] = tile[tx][kk];
    }
}

// ---- prep: folded conv weights (transposed) + biases ----------------------
__global__ void prep_wuwb(const float* __restrict__ cw, const float* __restrict__ cb) {
    int j = blockIdx.x;
    int k = threadIdx.x;
    int jh = j >> 1;
    float a = cw[jh * 256 + k];
    float c = cw[(128 + jh) * 256 + k];
    g_WUt[k * 256 + j] = a + c;
    g_WBt[k * 256 + j] = c;
    if (k == 0) {
        g_ub[j] = cb[jh] + cb[128 + jh];
        g_bb[j] = cb[128 + jh];
    }
}

// ---- packed f32x2 helpers (full-rate fp32 path on sm_103a) ----------------
__device__ __forceinline__ unsigned long long dup2(float a) {
    unsigned long long r;
    unsigned int ai = __float_as_uint(a);
    asm("mov.b64 %0, {%1, %1};" : "=l"(r) : "r"(ai));
    return r;
}
__device__ __forceinline__ void ffma2(unsigned long long& d, unsigned long long a,
                                      unsigned long long b) {
    asm("fma.rn.f32x2 %0, %1, %2, %0;" : "+l"(d) : "l"(a), "l"(b));
}
__device__ __forceinline__ float2 unp(unsigned long long v) {
    unsigned int lo, hi;
    asm("mov.b64 {%0, %1}, %2;" : "=r"(lo), "=r"(hi) : "l"(v));
    return make_float2(__uint_as_float(lo), __uint_as_float(hi));
}
__device__ __forceinline__ float gelu_exact(float x) {
    return 0.5f * x * (1.f + erff(x * 0.70710678118654752440f));
}

// ---- cp.async helpers -----------------------------------------------------
__device__ __forceinline__ void cp16(float* dst_s, const float* src_g) {
    unsigned sd = (unsigned)__cvta_generic_to_shared(dst_s);
    asm volatile("cp.async.cg.shared.global [%0], [%1], 16;\n" :: "r"(sd), "l"(src_g));
}
__device__ __forceinline__ void cp_commit() {
    asm volatile("cp.async.commit_group;\n");
}

// issue async copy of weight chunk kc (16 k-rows of 256 floats) into wbuf
__device__ __forceinline__ void load_chunk(const float* __restrict__ Wg,
                                           float* __restrict__ wbuf,
                                           int kc, int t) {
    const float* src = Wg + (((size_t)kc * 16) << 8);
#pragma unroll
    for (int r = 0; r < 4; r++) {
        int j = r * 256 + t;
        int k = j >> 6, o4 = (j & 63) << 2;
        cp16(wbuf + k * 264 + o4, src + (k << 8) + o4);
    }
    cp_commit();
}

// ---- core 256x32 GEMM over K=256, double-buffered cp.async weights --------
// Wg: global [k][o] (pre-transposed, pre-scaled).  src: SMEM [256][36].
// w2: SMEM 2 x [16][264] chunk buffers.
__device__ __forceinline__ void gemm256(const float* __restrict__ Wg,
                                        const float* __restrict__ src,
                                        float* __restrict__ w2,
                                        int o_base, int p_base, int t,
                                        unsigned long long acc[4][4]) {
    load_chunk(Wg, w2, 0, t);
    load_chunk(Wg, w2 + 16 * 264, 1, t);
#pragma unroll 1
    for (int kc = 0; kc < 16; kc++) {
        if (kc == 15) asm volatile("cp.async.wait_group 0;\n");
        else          asm volatile("cp.async.wait_group 1;\n");
        __syncthreads();
        const float* w_s = w2 + (kc & 1) * (16 * 264);
        const float* srck = src + kc * 16 * 36;
#pragma unroll
        for (int k = 0; k < 16; k++) {
            float4 wv = *(const float4*)(w_s + k * 264 + o_base);
            unsigned long long w0 = dup2(wv.x), w1 = dup2(wv.y);
            unsigned long long w2r = dup2(wv.z), w3 = dup2(wv.w);
            const float* ur = srck + k * 36 + p_base;
            ulonglong2 ua = *(const ulonglong2*)ur;
            ulonglong2 ub = *(const ulonglong2*)(ur + 4);
            ffma2(acc[0][0], w0, ua.x); ffma2(acc[0][1], w0, ua.y);
            ffma2(acc[0][2], w0, ub.x); ffma2(acc[0][3], w0, ub.y);
            ffma2(acc[1][0], w1, ua.x); ffma2(acc[1][1], w1, ua.y);
            ffma2(acc[1][2], w1, ub.x); ffma2(acc[1][3], w1, ub.y);
            ffma2(acc[2][0], w2r, ua.x); ffma2(acc[2][1], w2r, ua.y);
            ffma2(acc[2][2], w2r, ub.x); ffma2(acc[2][3], w2r, ub.y);
            ffma2(acc[3][0], w3, ua.x); ffma2(acc[3][1], w3, ua.y);
            ffma2(acc[3][2], w3, ub.x); ffma2(acc[3][3], w3, ub.y);
        }
        __syncthreads();
        if (kc < 14) load_chunk(Wg, w2 + (kc & 1) * (16 * 264), kc + 2, t);
    }
}

// ---- fused main kernel ----------------------------------------------------
// grid (128 tiles, 4 batches), 256 threads. Tile = 32 conv pixels (half a row).
// SMEM: u[256][36] | b[256][36] | w2[2][16][264]  = 107,520 B -> 2 CTAs/SM
__global__ __launch_bounds__(256, 2)
void fused_main(const float* __restrict__ x, float* __restrict__ out) {
    extern __shared__ float sm[];
    float* u_s = sm;            // 9216 floats
    float* b_s = sm + 9216;     // 9216 floats
    float* w2 = sm + 18432;     // 8448 floats (2 x 16 x 264)
    int t = threadIdx.x;
    int tile = blockIdx.x;      // 0..127
    int b = blockIdx.y;         // 0..3
    int o_base = (t & 63) << 2;
    int p_base = (t >> 6) << 3;
    int q0 = tile << 5;         // conv-pixel linear offset

    // stage input tile x[b][:, q0..q0+31] into b_s (temp use as GEMM src)
    {
        const float* xb = x + ((size_t)b << 20) + q0;
        int c0 = t >> 5, p = t & 31;
#pragma unroll
        for (int it = 0; it < 32; it++) {
            int c = c0 + (it << 3);
            b_s[c * 36 + p] = xb[((size_t)c << 12) + p];
        }
    }

    unsigned long long acc[4][4];

    // GEMM 0: u0 = WU * x + ub
#pragma unroll
    for (int oi = 0; oi < 4; oi++) {
        unsigned long long bi = dup2(g_ub[o_base + oi]);
#pragma unroll
        for (int pp = 0; pp < 4; pp++) acc[oi][pp] = bi;
    }
    gemm256(g_WUt, b_s, w2, o_base, p_base, t, acc);
#pragma unroll
    for (int oi = 0; oi < 4; oi++)
#pragma unroll
        for (int pp = 0; pp < 4; pp++)
            *(float2*)(u_s + (o_base + oi) * 36 + p_base + pp * 2) = unp(acc[oi][pp]);

    // GEMM 1: b0 = WB * x + bb   (overwrites b_s after full accumulation+sync)
#pragma unroll
    for (int oi = 0; oi < 4; oi++) {
        unsigned long long bi = dup2(g_bb[o_base + oi]);
#pragma unroll
        for (int pp = 0; pp < 4; pp++) acc[oi][pp] = bi;
    }
    gemm256(g_WBt, b_s, w2, o_base, p_base, t, acc);
    // safe to overwrite b_s: all accumulation done; each thread writes its own slots,
    // and the next GEMM's reads are fenced by its kc=0 barrier.
    __syncthreads();
#pragma unroll
    for (int oi = 0; oi < 4; oi++)
#pragma unroll
        for (int pp = 0; pp < 4; pp++)
            *(float2*)(b_s + (o_base + oi) * 36 + p_base + pp * 2) = unp(acc[oi][pp]);

    // 6 layers: h = WL*u ; b += gelu(h) ; u += b
    for (int l = 0; l < NUM_LAYERS; l++) {
#pragma unroll
        for (int oi = 0; oi < 4; oi++)
#pragma unroll
            for (int pp = 0; pp < 4; pp++) acc[oi][pp] = 0ull;
        const float* Wl = g_WLt + ((size_t)(l * 4 + b) << 16);
        gemm256(Wl, u_s, w2, o_base, p_base, t, acc);
#pragma unroll
        for (int oi = 0; oi < 4; oi++) {
#pragma unroll
            for (int pp = 0; pp < 4; pp++) {
                float2 h = unp(acc[oi][pp]);
                float* bp = b_s + (o_base + oi) * 36 + p_base + pp * 2;
                float* up = u_s + (o_base + oi) * 36 + p_base + pp * 2;
                float bn0 = bp[0] + gelu_exact(h.x);
                float bn1 = bp[1] + gelu_exact(h.y);
                bp[0] = bn0; bp[1] = bn1;
                up[0] += bn0; up[1] += bn1;
            }
        }
    }
    __syncthreads();

    // output: 0.5*u replicated 2x2, coalesced float2 stores
    {
        int qh = tile >> 1, qw0 = (tile & 1) << 5;
        float* ob = out + ((size_t)b << 22);
        int c0 = t >> 5, p = t & 31;
        int col = (qw0 + p) << 1;
        int row = qh << 1;
#pragma unroll
        for (int it = 0; it < 32; it++) {
            int c = c0 + (it << 3);
            float v = 0.5f * u_s[c * 36 + p];
            float2 vv = make_float2(v, v);
            float* pr = ob + (((size_t)c << 14) + ((size_t)row << 7) + col);
            *(float2*)pr = vv;
            *(float2*)(pr + 128) = vv;
        }
    }
}

// ---------------------------------------------------------------------------
extern "C" void kernel_launch(void* const* d_in, const int* in_sizes, int n_in,
                              void* d_out, int out_size) {
    const float* x  = (const float*)d_in[0];
    const float* y  = (const float*)d_in[1];
    const float* cw = (const float*)d_in[2];
    const float* cb = (const float*)d_in[3];
    const float* aw = (const float*)d_in[4];
    const float* ab = (const float*)d_in[5];
    const float* mw = (const float*)d_in[6];
    float* out = (float*)d_out;

    prep_alpha<<<dim3(256, NUM_LAYERS), 128>>>(aw, ab, mw, y);
    prep_wl<<<dim3(NUM_LAYERS * 4, 8, 8), dim3(32, 8)>>>(mw);
    prep_wuwb<<<256, 256>>>(cw, cb);

    cudaFuncSetAttribute(fused_main, cudaFuncAttributeMaxDynamicSharedMemorySize,
                         107520);
    fused_main<<<dim3(128, 4), 256, 107520>>>(x, out);
}

// round 6
// speedup vs baseline: 1.9360x; 1.9360x over previous
#include <cuda_runtime.h>
#include <cuda_bf16.h>
#include <cstdint>
#include <cstddef>

#define NUM_LAYERS 6

// ---------------------------------------------------------------------------
// Algebra (verified R1-R3): compute on 64x64 conv pixels; per-pixel state:
//   u (=x1+x2), bst (=x2).
//   ph0: bst = WB*x + bb          ph1: u = WU*x + ub
//   ph2..7 (layer l): h = WL[l,b]*u ; bst += gelu(h) ; u += bst
//   out = 0.5*u replicated 2x2.
// Engine: mma.sync.m16n8k16 bf16 (plain sm_103 PTX — tcgen05 unavailable in
// this harness's PTX target). Exact 2x2-term bf16 split, 4 passes, f32 accum.
// ---------------------------------------------------------------------------

__device__ float g_alpha[NUM_LAYERS * 4 * 256];
// per pb=phase*4+b (32): 16 k-steps x [hi 8KB | lo 8KB]; plane = [16k][256o]
// swizzled: elem idx within plane = k*256 + ((o>>3)^(k&7))*8 + (o&7)
__device__ __nv_bfloat16 g_w[4194304];  // 8 MB
__device__ float g_bias_u[256];
__device__ float g_bias_b[256];

// ========================= prep kernels ====================================
__global__ void prep_alpha(const float* __restrict__ affine_w,
                           const float* __restrict__ affine_b,
                           const float* __restrict__ mod_w,
                           const float* __restrict__ y) {
    int o = blockIdx.x, lay = blockIdx.y, t = threadIdx.x;  // 128 threads
    const float* awr = affine_w + ((size_t)(lay * 256 + o)) * 512;
    float s0 = 0.f, s1 = 0.f, s2 = 0.f, s3 = 0.f, q = 0.f;
    for (int i = t; i < 512; i += 128) {
        float a = awr[i];
        s0 += a * y[i]; s1 += a * y[512 + i];
        s2 += a * y[1024 + i]; s3 += a * y[1536 + i];
    }
    const float* mwr = mod_w + ((size_t)(lay * 256 + o)) * 256;
    for (int i = t; i < 256; i += 128) { float m = mwr[i]; q += m * m; }
#pragma unroll
    for (int d = 16; d >= 1; d >>= 1) {
        s0 += __shfl_xor_sync(0xffffffffu, s0, d);
        s1 += __shfl_xor_sync(0xffffffffu, s1, d);
        s2 += __shfl_xor_sync(0xffffffffu, s2, d);
        s3 += __shfl_xor_sync(0xffffffffu, s3, d);
        q  += __shfl_xor_sync(0xffffffffu, q, d);
    }
    __shared__ float red[4][5];
    int w = t >> 5;
    if ((t & 31) == 0) { red[w][0]=s0; red[w][1]=s1; red[w][2]=s2; red[w][3]=s3; red[w][4]=q; }
    __syncthreads();
    if (t == 0) {
        float S0=0,S1=0,S2=0,S3=0,Q=0;
#pragma unroll
        for (int i = 0; i < 4; i++) {
            S0+=red[i][0]; S1+=red[i][1]; S2+=red[i][2]; S3+=red[i][3]; Q+=red[i][4];
        }
        float bias = affine_b[lay * 256 + o];
        float S[4] = {S0, S1, S2, S3};
#pragma unroll
        for (int b = 0; b < 4; b++) {
            float sp = S[b] + bias + 1.f;
            g_alpha[(lay * 4 + b) * 256 + o] = sp * rsqrtf(sp * sp * Q + 1e-8f);
        }
    }
}

__global__ void prep_bias(const float* __restrict__ cb) {
    int j = threadIdx.x;  // 256
    float c2v = cb[128 + (j >> 1)];
    g_bias_b[j] = c2v;
    g_bias_u[j] = cb[j >> 1] + c2v;
}

// coalesced fill: thread writes consecutive packed offsets, inverts swizzle
__global__ void prep_w(const float* __restrict__ cw, const float* __restrict__ mw) {
    int pb = blockIdx.x;   // phase*4+b
    int ks = blockIdx.y;   // 0..15
    int phase = pb >> 2, b = pb & 3;
    size_t blk = ((size_t)(pb * 16 + ks)) * 8192;  // hi plane; lo at +4096
#pragma unroll 1
    for (int it = 0; it < 16; it++) {
        int e = it * 256 + threadIdx.x;      // 0..4095
        int kk = e >> 8;
        int cp = (e >> 3) & 31, l8 = e & 7;
        int o = ((cp ^ (kk & 7)) << 3) + l8;
        int k = ks * 16 + kk;
        float wv;
        if (phase == 0)      wv = cw[(128 + (o >> 1)) * 256 + k];
        else if (phase == 1) wv = cw[(o >> 1) * 256 + k] + cw[(128 + (o >> 1)) * 256 + k];
        else                 wv = mw[((size_t)((phase - 2) * 256 + o)) * 256 + k] *
                                  g_alpha[((phase - 2) * 4 + b) * 256 + o];
        __nv_bfloat16 hi = __float2bfloat16(wv);
        __nv_bfloat16 lo = __float2bfloat16(wv - __bfloat162float(hi));
        g_w[blk + e] = hi;
        g_w[blk + 4096 + e] = lo;
    }
}

// ========================= device helpers ==================================
__device__ __forceinline__ uint32_t bf2pack(float f0, float f1) {
    __nv_bfloat162 v;
    v.x = __float2bfloat16(f0);
    v.y = __float2bfloat16(f1);
    return *reinterpret_cast<uint32_t*>(&v);
}
__device__ __forceinline__ float2 bf2unpack(uint32_t w) {
    __nv_bfloat162 v = *reinterpret_cast<__nv_bfloat162*>(&w);
    return make_float2(__bfloat162float(v.x), __bfloat162float(v.y));
}
__device__ __forceinline__ float bflo(float f) {  // residual after bf16 round
    return f - __bfloat162float(__float2bfloat16(f));
}
__device__ __forceinline__ float gelu_exact(float x) {
    return 0.5f * x * (1.f + erff(x * 0.70710678118654752440f));
}
__device__ __forceinline__ void ldsm4t(uint32_t* d, uint32_t addr) {
    asm volatile("ldmatrix.sync.aligned.m8n8.x4.trans.shared.b16 {%0,%1,%2,%3}, [%4];"
                 : "=r"(d[0]), "=r"(d[1]), "=r"(d[2]), "=r"(d[3]) : "r"(addr));
}
__device__ __forceinline__ void mma16816(float* c, const uint32_t* a, const uint32_t* b) {
    asm volatile(
        "mma.sync.aligned.m16n8k16.row.col.f32.bf16.bf16.f32 "
        "{%0,%1,%2,%3}, {%4,%5,%6,%7}, {%8,%9}, {%0,%1,%2,%3};"
        : "+f"(c[0]), "+f"(c[1]), "+f"(c[2]), "+f"(c[3])
        : "r"(a[0]), "r"(a[1]), "r"(a[2]), "r"(a[3]), "r"(b[0]), "r"(b[1]));
}
__device__ __forceinline__ void cp16(void* dst_s, const void* src_g) {
    unsigned sd = (unsigned)__cvta_generic_to_shared(dst_s);
    asm volatile("cp.async.cg.shared.global [%0], [%1], 16;\n" :: "r"(sd), "l"(src_g));
}
// one 16KB weight k-step (hi+lo planes) into ring slot ks&3
__device__ __forceinline__ void issue_stage(const char* wph, char* ringp, int ks, int t) {
    const char* src = wph + (size_t)ks * 16384;
    char* dst = ringp + ((ks & 3) << 14);
    cp16(dst + t * 16, src + t * 16);
    cp16(dst + 8192 + t * 16, src + 8192 + t * 16);
    asm volatile("cp.async.commit_group;\n");
}

// 2 m-tiles x 4 n-tiles of mma into acc
__device__ __forceinline__ void mma8(float acc[2][4][4], uint32_t A[2][4],
                                     const uint32_t* B0, const uint32_t* B1) {
#pragma unroll
    for (int mt = 0; mt < 2; mt++) {
#pragma unroll
        for (int j = 0; j < 4; j++) {
            const uint32_t* bp = (j < 2) ? (B0 + (j & 1) * 2) : (B1 + (j & 1) * 2);
            mma16816(acc[mt][j], A[mt], bp);
        }
    }
}

// SMEM byte map
#define U_HI 0
#define U_LO 36864
#define RING 73728
#define SMEM_BYTES 139264

// ========================= fused main ======================================
// grid (64 px-tiles, 4 batches), 512 threads, 1 CTA/SM.
// u planes: [256 ch][64 px] bf16, rows padded to 144B (conflict-free ldsm).
__global__ __launch_bounds__(512, 1)
void fused_mma(const float* __restrict__ x, float* __restrict__ out) {
    extern __shared__ char sm[];
    uint32_t smb;
    asm("{ .reg .u64 t; cvta.to.shared.u64 t, %1; cvt.u32.u64 %0, t; }"
        : "=r"(smb) : "l"(sm));
    const int t = threadIdx.x, lane = t & 31, wid = t >> 5;
    const int tile = blockIdx.x, b = blockIdx.y;

    const char* wb_all = (const char*)g_w;
    // prime phase 0 stages 0..2
    {
        const char* wph = wb_all + ((size_t)(0 * 4 + b)) * 262144;
        issue_stage(wph, sm + RING, 0, t);
        issue_stage(wph, sm + RING, 1, t);
        issue_stage(wph, sm + RING, 2, t);
    }

    // ---- stage input x tile into u planes (bf16 split) ----
    {
        const float* xb = x + ((size_t)b << 20) + tile * 64;
#pragma unroll
        for (int it = 0; it < 8; it++) {
            int e4 = it * 512 + t;
            int c = e4 >> 4, p = (e4 & 15) * 4;
            float4 v = *(const float4*)(xb + ((size_t)c << 12) + p);
            uint32_t off = c * 144 + p * 2;
            uint2 hw, lw;
            hw.x = bf2pack(v.x, v.y); hw.y = bf2pack(v.z, v.w);
            lw.x = bf2pack(bflo(v.x), bflo(v.y)); lw.y = bf2pack(bflo(v.z), bflo(v.w));
            *(uint2*)(sm + U_HI + off) = hw;
            *(uint2*)(sm + U_LO + off) = lw;
        }
    }
    __syncthreads();

    // lane/warp constants
    const int g = lane >> 2, tq = lane & 3;
    const int q = lane >> 3, r = lane & 7;
    const int o_base = (wid >> 1) * 32, px_base = (wid & 1) * 32;
    const int krow = r + ((q >> 1) << 3);
    uint32_t aoff[2], boff[2];
#pragma unroll
    for (int mt = 0; mt < 2; mt++) {
        int oo = o_base + mt * 16 + ((q & 1) << 3);
        aoff[mt] = krow * 512 + ((((oo >> 3) ^ (krow & 7))) << 4);
    }
    const int chl = r + ((q & 1) << 3);
#pragma unroll
    for (int h = 0; h < 2; h++) {
        int po = px_base + h * 16 + ((q >> 1) << 3);
        boff[h] = chl * 144 + po * 2;
    }
    float bb_[2][2], bu_[2][2];
#pragma unroll
    for (int mt = 0; mt < 2; mt++)
#pragma unroll
        for (int i2 = 0; i2 < 2; i2++) {
            int o_r = o_base + mt * 16 + g + i2 * 8;
            bb_[mt][i2] = g_bias_b[o_r];
            bu_[mt][i2] = g_bias_u[o_r];
        }

    float bst[2][4][4];

#pragma unroll 1
    for (int phase = 0; phase < 8; phase++) {
        const char* wph = wb_all + ((size_t)(phase * 4 + b)) * 262144;
        float acc[2][4][4];
#pragma unroll
        for (int mt = 0; mt < 2; mt++)
#pragma unroll
            for (int j = 0; j < 4; j++)
#pragma unroll
                for (int i = 0; i < 4; i++) acc[mt][j][i] = 0.f;

#pragma unroll 1
        for (int ks = 0; ks < 16; ks++) {
            if (ks < 14)       asm volatile("cp.async.wait_group 2;\n");
            else if (ks == 14) asm volatile("cp.async.wait_group 1;\n");
            else               asm volatile("cp.async.wait_group 0;\n");
            __syncthreads();
            uint32_t stg = smb + RING + ((uint32_t)(ks & 3) << 14);
            uint32_t uh = smb + U_HI + ks * 2304;
            uint32_t ul = smb + U_LO + ks * 2304;
            uint32_t A[2][4], B0[4], B1[4], C0[4], C1[4];
            // pass 1: Whi * uhi
            ldsm4t(A[0], stg + aoff[0]);
            ldsm4t(A[1], stg + aoff[1]);
            ldsm4t(B0, uh + boff[0]);
            ldsm4t(B1, uh + boff[1]);
            mma8(acc, A, B0, B1);
            // pass 2: Whi * ulo
            ldsm4t(C0, ul + boff[0]);
            ldsm4t(C1, ul + boff[1]);
            mma8(acc, A, C0, C1);
            // pass 3+4: Wlo * uhi, Wlo * ulo
            ldsm4t(A[0], stg + 8192 + aoff[0]);
            ldsm4t(A[1], stg + 8192 + aoff[1]);
            mma8(acc, A, B0, B1);
            mma8(acc, A, C0, C1);
            if (ks <= 12) issue_stage(wph, sm + RING, ks + 3, t);
        }
        __syncthreads();   // all ldsm of u done before epilogue overwrites
        if (phase < 7) {   // prime next phase during epilogue
            const char* wnx = wb_all + ((size_t)((phase + 1) * 4 + b)) * 262144;
            issue_stage(wnx, sm + RING, 0, t);
            issue_stage(wnx, sm + RING, 1, t);
            issue_stage(wnx, sm + RING, 2, t);
        }

        // ---- epilogue (thread-owned fragment elements) ----
#pragma unroll
        for (int mt = 0; mt < 2; mt++)
#pragma unroll
        for (int nt = 0; nt < 4; nt++)
#pragma unroll
        for (int i2 = 0; i2 < 2; i2++) {
            float h0 = acc[mt][nt][i2 * 2], h1 = acc[mt][nt][i2 * 2 + 1];
            int o_r = o_base + mt * 16 + g + i2 * 8;
            int px_p = px_base + nt * 8 + tq * 2;
            uint32_t off = o_r * 144 + px_p * 2;
            if (phase == 0) {
                bst[mt][nt][i2 * 2]     = h0 + bb_[mt][i2];
                bst[mt][nt][i2 * 2 + 1] = h1 + bb_[mt][i2];
            } else if (phase == 1) {
                float u0 = h0 + bu_[mt][i2], u1 = h1 + bu_[mt][i2];
                *(uint32_t*)(sm + U_HI + off) = bf2pack(u0, u1);
                *(uint32_t*)(sm + U_LO + off) = bf2pack(bflo(u0), bflo(u1));
            } else {
                float2 uhv = bf2unpack(*(uint32_t*)(sm + U_HI + off));
                float2 ulv = bf2unpack(*(uint32_t*)(sm + U_LO + off));
                float u0 = uhv.x + ulv.x, u1 = uhv.y + ulv.y;
                float* bs = &bst[mt][nt][i2 * 2];
                bs[0] += gelu_exact(h0);
                bs[1] += gelu_exact(h1);
                float un0 = u0 + bs[0], un1 = u1 + bs[1];
                if (phase == 7) {
                    float v0 = 0.5f * un0, v1 = 0.5f * un1;
                    float4 vv = make_float4(v0, v0, v1, v1);
                    float* pr = out + ((size_t)b << 22) + ((size_t)o_r << 14) +
                                (tile << 8) + px_p * 2;
                    *(float4*)pr = vv;
                    *(float4*)(pr + 128) = vv;
                } else {
                    *(uint32_t*)(sm + U_HI + off) = bf2pack(un0, un1);
                    *(uint32_t*)(sm + U_LO + off) = bf2pack(bflo(un0), bflo(un1));
                }
            }
        }
        __syncthreads();   // u writes visible before next phase's ldsm
    }
}

// ---------------------------------------------------------------------------
extern "C" void kernel_launch(void* const* d_in, const int* in_sizes, int n_in,
                              void* d_out, int out_size) {
    const float* x  = (const float*)d_in[0];
    const float* y  = (const float*)d_in[1];
    const float* cw = (const float*)d_in[2];
    const float* cb = (const float*)d_in[3];
    const float* aw = (const float*)d_in[4];
    const float* ab = (const float*)d_in[5];
    const float* mw = (const float*)d_in[6];
    float* out = (float*)d_out;

    prep_alpha<<<dim3(256, NUM_LAYERS), 128>>>(aw, ab, mw, y);
    prep_bias<<<1, 256>>>(cb);
    prep_w<<<dim3(32, 16), 256>>>(cw, mw);

    cudaFuncSetAttribute(fused_mma, cudaFuncAttributeMaxDynamicSharedMemorySize,
                         SMEM_BYTES);
    fused_mma<<<dim3(64, 4), 512, SMEM_BYTES>>>(x, out);
}

// round 7
// speedup vs baseline: 2.2517x; 1.1630x over previous
#include <cuda_runtime.h>
#include <cuda_bf16.h>
#include <cstdint>
#include <cstddef>

#define NUM_LAYERS 6

// ---------------------------------------------------------------------------
// Algebra (verified): compute on 64x64 conv pixels; per-pixel state:
//   u (=x1+x2), bst (=x2).
//   ph0: bst = WB*x + bb          ph1: u = WU*x + ub
//   ph2..7 (layer l): h = WL[l,b]*u ; bst += gelu(h) ; u += bst
//   out = 0.5*u replicated 2x2.
// Engine: mma.sync.m16n8k16 bf16, 2-term bf16 split both operands, 3 passes
// (hi*hi + hi*lo + lo*hi; lo*lo dropped, ~1.5e-5 rel contribution), f32 accum.
// R7: 256-thread CTAs (32px tile), 104KB smem -> 2 CTAs/SM co-resident.
// ---------------------------------------------------------------------------

__device__ float g_alpha[NUM_LAYERS * 4 * 256];
// per pb=phase*4+b (32): 16 k-steps x [hi 8KB | lo 8KB]; plane = [16k][256o]
// swizzled: elem idx within plane = k*256 + ((o>>3)^(k&7))*8 + (o&7)
__device__ __nv_bfloat16 g_w[4194304];  // 8 MB
__device__ float g_bias_u[256];
__device__ float g_bias_b[256];

// ========================= prep kernels ====================================
__global__ void prep_alpha(const float* __restrict__ affine_w,
                           const float* __restrict__ affine_b,
                           const float* __restrict__ mod_w,
                           const float* __restrict__ y) {
    int o = blockIdx.x, lay = blockIdx.y, t = threadIdx.x;  // 128 threads
    const float* awr = affine_w + ((size_t)(lay * 256 + o)) * 512;
    float s0 = 0.f, s1 = 0.f, s2 = 0.f, s3 = 0.f, q = 0.f;
    for (int i = t; i < 512; i += 128) {
        float a = awr[i];
        s0 += a * y[i]; s1 += a * y[512 + i];
        s2 += a * y[1024 + i]; s3 += a * y[1536 + i];
    }
    const float* mwr = mod_w + ((size_t)(lay * 256 + o)) * 256;
    for (int i = t; i < 256; i += 128) { float m = mwr[i]; q += m * m; }
#pragma unroll
    for (int d = 16; d >= 1; d >>= 1) {
        s0 += __shfl_xor_sync(0xffffffffu, s0, d);
        s1 += __shfl_xor_sync(0xffffffffu, s1, d);
        s2 += __shfl_xor_sync(0xffffffffu, s2, d);
        s3 += __shfl_xor_sync(0xffffffffu, s3, d);
        q  += __shfl_xor_sync(0xffffffffu, q, d);
    }
    __shared__ float red[4][5];
    int w = t >> 5;
    if ((t & 31) == 0) { red[w][0]=s0; red[w][1]=s1; red[w][2]=s2; red[w][3]=s3; red[w][4]=q; }
    __syncthreads();
    if (t == 0) {
        float S0=0,S1=0,S2=0,S3=0,Q=0;
#pragma unroll
        for (int i = 0; i < 4; i++) {
            S0+=red[i][0]; S1+=red[i][1]; S2+=red[i][2]; S3+=red[i][3]; Q+=red[i][4];
        }
        float bias = affine_b[lay * 256 + o];
        float S[4] = {S0, S1, S2, S3};
#pragma unroll
        for (int b = 0; b < 4; b++) {
            float sp = S[b] + bias + 1.f;
            g_alpha[(lay * 4 + b) * 256 + o] = sp * rsqrtf(sp * sp * Q + 1e-8f);
        }
    }
}

__global__ void prep_bias(const float* __restrict__ cb) {
    int j = threadIdx.x;  // 256
    float c2v = cb[128 + (j >> 1)];
    g_bias_b[j] = c2v;
    g_bias_u[j] = cb[j >> 1] + c2v;
}

// coalesced fill: thread writes consecutive packed offsets, inverts swizzle
__global__ void prep_w(const float* __restrict__ cw, const float* __restrict__ mw) {
    int pb = blockIdx.x;   // phase*4+b
    int ks = blockIdx.y;   // 0..15
    int phase = pb >> 2, b = pb & 3;
    size_t blk = ((size_t)(pb * 16 + ks)) * 8192;  // hi plane; lo at +4096
#pragma unroll 1
    for (int it = 0; it < 16; it++) {
        int e = it * 256 + threadIdx.x;      // 0..4095
        int kk = e >> 8;
        int cp = (e >> 3) & 31, l8 = e & 7;
        int o = ((cp ^ (kk & 7)) << 3) + l8;
        int k = ks * 16 + kk;
        float wv;
        if (phase == 0)      wv = cw[(128 + (o >> 1)) * 256 + k];
        else if (phase == 1) wv = cw[(o >> 1) * 256 + k] + cw[(128 + (o >> 1)) * 256 + k];
        else                 wv = mw[((size_t)((phase - 2) * 256 + o)) * 256 + k] *
                                  g_alpha[((phase - 2) * 4 + b) * 256 + o];
        __nv_bfloat16 hi = __float2bfloat16(wv);
        __nv_bfloat16 lo = __float2bfloat16(wv - __bfloat162float(hi));
        g_w[blk + e] = hi;
        g_w[blk + 4096 + e] = lo;
    }
}

// ========================= device helpers ==================================
__device__ __forceinline__ uint32_t bf2pack(float f0, float f1) {
    __nv_bfloat162 v;
    v.x = __float2bfloat16(f0);
    v.y = __float2bfloat16(f1);
    return *reinterpret_cast<uint32_t*>(&v);
}
__device__ __forceinline__ float2 bf2unpack(uint32_t w) {
    __nv_bfloat162 v = *reinterpret_cast<__nv_bfloat162*>(&w);
    return make_float2(__bfloat162float(v.x), __bfloat162float(v.y));
}
__device__ __forceinline__ float bflo(float f) {  // residual after bf16 round
    return f - __bfloat162float(__float2bfloat16(f));
}
__device__ __forceinline__ float gelu_exact(float x) {
    return 0.5f * x * (1.f + erff(x * 0.70710678118654752440f));
}
__device__ __forceinline__ void ldsm4t(uint32_t* d, uint32_t addr) {
    asm volatile("ldmatrix.sync.aligned.m8n8.x4.trans.shared.b16 {%0,%1,%2,%3}, [%4];"
                 : "=r"(d[0]), "=r"(d[1]), "=r"(d[2]), "=r"(d[3]) : "r"(addr));
}
__device__ __forceinline__ void mma16816(float* c, const uint32_t* a, const uint32_t* b) {
    asm volatile(
        "mma.sync.aligned.m16n8k16.row.col.f32.bf16.bf16.f32 "
        "{%0,%1,%2,%3}, {%4,%5,%6,%7}, {%8,%9}, {%0,%1,%2,%3};"
        : "+f"(c[0]), "+f"(c[1]), "+f"(c[2]), "+f"(c[3])
        : "r"(a[0]), "r"(a[1]), "r"(a[2]), "r"(a[3]), "r"(b[0]), "r"(b[1]));
}
__device__ __forceinline__ void cp16(void* dst_s, const void* src_g) {
    unsigned sd = (unsigned)__cvta_generic_to_shared(dst_s);
    asm volatile("cp.async.cg.shared.global [%0], [%1], 16;\n" :: "r"(sd), "l"(src_g));
}
// one 16KB weight k-step (hi+lo planes) into ring slot ks&3 (256 threads)
__device__ __forceinline__ void issue_stage(const char* wph, char* ringp, int ks, int t) {
    const char* src = wph + (size_t)ks * 16384;
    char* dst = ringp + ((ks & 3) << 14);
#pragma unroll
    for (int r = 0; r < 4; r++)
        cp16(dst + r * 4096 + t * 16, src + r * 4096 + t * 16);
    asm volatile("cp.async.commit_group;\n");
}

// 2 m-tiles x 4 n-tiles of mma into acc
__device__ __forceinline__ void mma8(float acc[2][4][4], uint32_t A[2][4],
                                     const uint32_t* B0, const uint32_t* B1) {
#pragma unroll
    for (int mt = 0; mt < 2; mt++) {
#pragma unroll
        for (int j = 0; j < 4; j++) {
            const uint32_t* bp = (j < 2) ? (B0 + (j & 1) * 2) : (B1 + (j & 1) * 2);
            mma16816(acc[mt][j], A[mt], bp);
        }
    }
}

// SMEM byte map: u planes [256 ch][32 px] bf16, row stride 80 B
#define U_HI 0
#define U_LO 20480
#define RING 40960
#define SMEM_BYTES 106496

// ========================= fused main ======================================
// grid (128 px-tiles, 4 batches), 256 threads, 2 CTAs/SM co-resident.
__global__ __launch_bounds__(256, 2)
void fused_mma(const float* __restrict__ x, float* __restrict__ out) {
    extern __shared__ char sm[];
    uint32_t smb;
    asm("{ .reg .u64 t; cvta.to.shared.u64 t, %1; cvt.u32.u64 %0, t; }"
        : "=r"(smb) : "l"(sm));
    const int t = threadIdx.x, lane = t & 31, wid = t >> 5;
    const int tile = blockIdx.x, b = blockIdx.y;

    const char* wb_all = (const char*)g_w;
    // prime phase 0 stages 0..2
    {
        const char* wph = wb_all + ((size_t)b) * 262144;
        issue_stage(wph, sm + RING, 0, t);
        issue_stage(wph, sm + RING, 1, t);
        issue_stage(wph, sm + RING, 2, t);
    }

    // ---- stage input x tile (32 px) into u planes (bf16 split) ----
    {
        const float* xb = x + ((size_t)b << 20) + tile * 32;
#pragma unroll
        for (int it = 0; it < 8; it++) {
            int e4 = it * 256 + t;            // 0..2047 float4s
            int c = e4 >> 3, p = (e4 & 7) * 4;
            float4 v = *(const float4*)(xb + ((size_t)c << 12) + p);
            uint32_t off = c * 80 + p * 2;
            uint2 hw, lw;
            hw.x = bf2pack(v.x, v.y); hw.y = bf2pack(v.z, v.w);
            lw.x = bf2pack(bflo(v.x), bflo(v.y)); lw.y = bf2pack(bflo(v.z), bflo(v.w));
            *(uint2*)(sm + U_HI + off) = hw;
            *(uint2*)(sm + U_LO + off) = lw;
        }
    }
    __syncthreads();

    // lane/warp constants
    const int g = lane >> 2, tq = lane & 3;
    const int q = lane >> 3, r = lane & 7;
    const int o_base = wid * 32;             // 8 warps cover 256 channels
    const int krow = r + ((q >> 1) << 3);
    uint32_t aoff[2], boff[2];
#pragma unroll
    for (int mt = 0; mt < 2; mt++) {
        int oo = o_base + mt * 16 + ((q & 1) << 3);
        aoff[mt] = krow * 512 + ((((oo >> 3) ^ (krow & 7))) << 4);
    }
    const int chl = r + ((q & 1) << 3);
#pragma unroll
    for (int h = 0; h < 2; h++) {
        int po = h * 16 + ((q >> 1) << 3);
        boff[h] = chl * 80 + po * 2;
    }
    float bb_[2][2], bu_[2][2];
#pragma unroll
    for (int mt = 0; mt < 2; mt++)
#pragma unroll
        for (int i2 = 0; i2 < 2; i2++) {
            int o_r = o_base + mt * 16 + g + i2 * 8;
            bb_[mt][i2] = g_bias_b[o_r];
            bu_[mt][i2] = g_bias_u[o_r];
        }

    float bst[2][4][4];

#pragma unroll 1
    for (int phase = 0; phase < 8; phase++) {
        const char* wph = wb_all + ((size_t)(phase * 4 + b)) * 262144;
        float acc[2][4][4];
#pragma unroll
        for (int mt = 0; mt < 2; mt++)
#pragma unroll
            for (int j = 0; j < 4; j++)
#pragma unroll
                for (int i = 0; i < 4; i++) acc[mt][j][i] = 0.f;

#pragma unroll 1
        for (int ks = 0; ks < 16; ks++) {
            if (ks < 14)       asm volatile("cp.async.wait_group 2;\n");
            else if (ks == 14) asm volatile("cp.async.wait_group 1;\n");
            else               asm volatile("cp.async.wait_group 0;\n");
            __syncthreads();
            uint32_t stg = smb + RING + ((uint32_t)(ks & 3) << 14);
            uint32_t uh = smb + U_HI + ks * 1280;
            uint32_t ul = smb + U_LO + ks * 1280;
            uint32_t A[2][4], B0[4], B1[4], C0[4], C1[4];
            // pass 1: Whi * uhi
            ldsm4t(A[0], stg + aoff[0]);
            ldsm4t(A[1], stg + aoff[1]);
            ldsm4t(B0, uh + boff[0]);
            ldsm4t(B1, uh + boff[1]);
            mma8(acc, A, B0, B1);
            // pass 2: Whi * ulo
            ldsm4t(C0, ul + boff[0]);
            ldsm4t(C1, ul + boff[1]);
            mma8(acc, A, C0, C1);
            // pass 3: Wlo * uhi   (lo*lo dropped: ~2^-16 relative)
            ldsm4t(A[0], stg + 8192 + aoff[0]);
            ldsm4t(A[1], stg + 8192 + aoff[1]);
            mma8(acc, A, B0, B1);
            if (ks <= 12) issue_stage(wph, sm + RING, ks + 3, t);
        }
        __syncthreads();   // all ldsm of u done before epilogue overwrites
        if (phase < 7) {   // prime next phase during epilogue
            const char* wnx = wb_all + ((size_t)((phase + 1) * 4 + b)) * 262144;
            issue_stage(wnx, sm + RING, 0, t);
            issue_stage(wnx, sm + RING, 1, t);
            issue_stage(wnx, sm + RING, 2, t);
        }

        // ---- epilogue (thread-owned fragment elements) ----
#pragma unroll
        for (int mt = 0; mt < 2; mt++)
#pragma unroll
        for (int nt = 0; nt < 4; nt++)
#pragma unroll
        for (int i2 = 0; i2 < 2; i2++) {
            float h0 = acc[mt][nt][i2 * 2], h1 = acc[mt][nt][i2 * 2 + 1];
            int o_r = o_base + mt * 16 + g + i2 * 8;
            int px_p = nt * 8 + tq * 2;
            uint32_t off = o_r * 80 + px_p * 2;
            if (phase == 0) {
                bst[mt][nt][i2 * 2]     = h0 + bb_[mt][i2];
                bst[mt][nt][i2 * 2 + 1] = h1 + bb_[mt][i2];
            } else if (phase == 1) {
                float u0 = h0 + bu_[mt][i2], u1 = h1 + bu_[mt][i2];
                *(uint32_t*)(sm + U_HI + off) = bf2pack(u0, u1);
                *(uint32_t*)(sm + U_LO + off) = bf2pack(bflo(u0), bflo(u1));
            } else {
                float2 uhv = bf2unpack(*(uint32_t*)(sm + U_HI + off));
                float2 ulv = bf2unpack(*(uint32_t*)(sm + U_LO + off));
                float u0 = uhv.x + ulv.x, u1 = uhv.y + ulv.y;
                float* bs = &bst[mt][nt][i2 * 2];
                bs[0] += gelu_exact(h0);
                bs[1] += gelu_exact(h1);
                float un0 = u0 + bs[0], un1 = u1 + bs[1];
                if (phase == 7) {
                    int q0 = tile * 32 + px_p;
                    int qh = q0 >> 6, qw = q0 & 63;
                    float v0 = 0.5f * un0, v1 = 0.5f * un1;
                    float4 vv = make_float4(v0, v0, v1, v1);
                    float* pr = out + ((size_t)b << 22) + ((size_t)o_r << 14) +
                                ((size_t)(qh * 2) << 7) + qw * 2;
                    *(float4*)pr = vv;
                    *(float4*)(pr + 128) = vv;
                } else {
                    *(uint32_t*)(sm + U_HI + off) = bf2pack(un0, un1);
                    *(uint32_t*)(sm + U_LO + off) = bf2pack(bflo(un0), bflo(un1));
                }
            }
        }
        __syncthreads();   // u writes visible before next phase's ldsm
    }
}

// ---------------------------------------------------------------------------
extern "C" void kernel_launch(void* const* d_in, const int* in_sizes, int n_in,
                              void* d_out, int out_size) {
    const float* x  = (const float*)d_in[0];
    const float* y  = (const float*)d_in[1];
    const float* cw = (const float*)d_in[2];
    const float* cb = (const float*)d_in[3];
    const float* aw = (const float*)d_in[4];
    const float* ab = (const float*)d_in[5];
    const float* mw = (const float*)d_in[6];
    float* out = (float*)d_out;

    prep_alpha<<<dim3(256, NUM_LAYERS), 128>>>(aw, ab, mw, y);
    prep_bias<<<1, 256>>>(cb);
    prep_w<<<dim3(32, 16), 256>>>(cw, mw);

    cudaFuncSetAttribute(fused_mma, cudaFuncAttributeMaxDynamicSharedMemorySize,
                         SMEM_BYTES);
    fused_mma<<<dim3(128, 4), 256, SMEM_BYTES>>>(x, out);
}